// round 17
// baseline (speedup 1.0000x reference)
#include <cuda_runtime.h>
#include <cstdint>

// Problem constants
#define BB   4
#define TT   2048
#define CC   1024
#define HH   16
#define DD   64
#define MROWS (BB*TT)      // 8192

// Scratch (static device globals — accessed ONLY via symbol inside kernels;
// never passed as kernel arguments from host code).
__device__ float g_q[BB*HH*TT*DD];   // [B,H,T,d]
__device__ float g_k[BB*HH*TT*DD];
__device__ float g_v[BB*HH*TT*DD];
__device__ float g_y[BB*TT*CC];      // attention output, [B,T,C]

// ============================================================================
// Packed f32x2 + cp.async helpers
// ============================================================================
typedef unsigned long long u64;

__device__ __forceinline__ u64 pack2(float x) {
    u64 r;
    asm("mov.b64 %0, {%1, %1};" : "=l"(r) : "f"(x));
    return r;
}
__device__ __forceinline__ void ffma2(u64& d, u64 a, u64 b) {
    asm("fma.rn.f32x2 %0, %1, %2, %0;" : "+l"(d) : "l"(a), "l"(b));
}
__device__ __forceinline__ void fmul2(u64& d, u64 a) {
    asm("mul.rn.f32x2 %0, %0, %1;" : "+l"(d) : "l"(a));
}
__device__ __forceinline__ void unpack2(u64 v, float& lo, float& hi) {
    asm("mov.b64 {%0, %1}, %2;" : "=f"(lo), "=f"(hi) : "l"(v));
}
__device__ __forceinline__ uint32_t smem_u32_of(const void* p) {
    uint32_t a;
    asm("{ .reg .u64 t; cvta.to.shared.u64 t, %1; cvt.u32.u64 %0, t; }"
        : "=r"(a) : "l"(p));
    return a;
}
#define CPG16(dst_sm, src) \
    asm volatile("cp.async.cg.shared.global [%0], [%1], 16;" \
                 :: "r"(dst_sm), "l"(src))
#define CP_COMMIT() asm volatile("cp.async.commit_group;" ::: "memory")
#define CP_WAIT0()  asm volatile("cp.async.wait_group 0;" ::: "memory")

// ============================================================================
// Packed-FMA GEMM, double-buffered, BK=8, 2 CTA/SM.
// Round-17: mainloop unrolled by 2 (buffer index is a compile-time literal
// in each phase -> smem addresses are base+immediate) and global pointers
// strength-reduced (increments, no per-iteration multiplies).
// ============================================================================
// One pipeline phase: compute on buffer CUR while prefetching into NXT.
// aptr/bptr are advanced by the caller between phases.
#define GEMM_PHASE(CUR, NXT, LAST)                                            \
    do {                                                                      \
        float4 av, bv;                                                        \
        if (!(LAST)) {                                                        \
            av = *(const float4*)aptr;                                        \
            bv = *(const float4*)bptr;                                        \
        }                                                                     \
        _Pragma("unroll")                                                     \
        for (int kk = 0; kk < 8; kk++) {                                      \
            float a[8];                                                       \
            *(float4*)&a[0] = *(float4*)&As[CUR][kk][row8];                   \
            *(float4*)&a[4] = *(float4*)&As[CUR][kk][row8 + 4];               \
            float4 b0 = *(float4*)&Bs[CUR][kk][4 * tx];                       \
            float4 b1 = *(float4*)&Bs[CUR][kk][64 + 4 * tx];                  \
            u64 bp0 = ((const u64*)&b0)[0];                                   \
            u64 bp1 = ((const u64*)&b0)[1];                                   \
            u64 bp2 = ((const u64*)&b1)[0];                                   \
            u64 bp3 = ((const u64*)&b1)[1];                                   \
            _Pragma("unroll")                                                 \
            for (int i = 0; i < 8; i++) {                                     \
                u64 ap = pack2(a[i]);                                         \
                ffma2(acc2[i][0], ap, bp0);                                   \
                ffma2(acc2[i][1], ap, bp1);                                   \
                ffma2(acc2[i][2], ap, bp2);                                   \
                ffma2(acc2[i][3], ap, bp3);                                   \
            }                                                                 \
        }                                                                     \
        if (!(LAST)) {                                                        \
            As[NXT][aq + 0][ar] = av.x; As[NXT][aq + 1][ar] = av.y;           \
            As[NXT][aq + 2][ar] = av.z; As[NXT][aq + 3][ar] = av.w;           \
            *(float4*)&Bs[NXT][bk][4 * bc] = bv;                              \
            aptr += 8;                                                        \
            bptr += bstride;                                                  \
        }                                                                     \
        __syncthreads();                                                      \
    } while (0)

__global__ __launch_bounds__(256, 2)
void qkv_p2_kernel(const float* __restrict__ Ag, const float* __restrict__ Wg,
                   const float* __restrict__ bias)
{
    __shared__ float As[2][8][132];   // k-major: As[buf][k][m]
    __shared__ float Bs[2][8][132];   // Bs[buf][k][interleaved n]

    const int tid  = threadIdx.x;
    const int ty   = tid >> 4, tx = tid & 15;
    const int row8 = ty * 8,  col8 = tx * 8;
    const int m0   = blockIdx.y * 128;
    const int n0   = blockIdx.x * 128;

    const int ar = tid >> 1;                 // A row 0..127
    const int aq = (tid & 1) * 4;            // A k-offset 0 or 4
    const int bk = tid >> 5;                 // B k row 0..7
    const int bc = tid & 31;                 // B physical chunk
    const int bj = (((bc & 15) << 1) | (bc >> 4)) * 4;

    const size_t bstride = (size_t)8 * 3072;
    const float* aptr = Ag + (size_t)(m0 + ar) * 1024 + aq;
    const float* bptr = Wg + (size_t)bk * 3072 + n0 + bj;

    u64 acc2[8][4];
#pragma unroll
    for (int i = 0; i < 8; i++)
#pragma unroll
        for (int j = 0; j < 4; j++) acc2[i][j] = 0ull;

    // Prologue: chunk 0 -> buf 0; advance pointers to chunk 1
    {
        float4 av = *(const float4*)aptr;
        float4 bv = *(const float4*)bptr;
        As[0][aq + 0][ar] = av.x; As[0][aq + 1][ar] = av.y;
        As[0][aq + 2][ar] = av.z; As[0][aq + 3][ar] = av.w;
        *(float4*)&Bs[0][bk][4 * bc] = bv;
        aptr += 8;
        bptr += bstride;
    }
    __syncthreads();

    // 128 chunks: 63 full double-phases + final pair with no prefetch on last
    for (int s = 0; s < 63; s++) {
        GEMM_PHASE(0, 1, false);
        GEMM_PHASE(1, 0, false);
    }
    GEMM_PHASE(0, 1, false);
    GEMM_PHASE(1, 0, true);

    // Epilogue: unpack, bias add, scatter to g_q/g_k/g_v
    float bvv[8];
#pragma unroll
    for (int j = 0; j < 8; j++) bvv[j] = bias[n0 + col8 + j];

    int sel = (n0 + col8) >> 10;
    int cc0 = (n0 + col8) & 1023;
    int h   = cc0 >> 6;
    int dd  = cc0 & 63;
    float* dst = (sel == 0) ? g_q : ((sel == 1) ? g_k : g_v);
#pragma unroll
    for (int i = 0; i < 8; i++) {
        float acc[8];
#pragma unroll
        for (int jp = 0; jp < 4; jp++)
            unpack2(acc2[i][jp], acc[2 * jp], acc[2 * jp + 1]);
        int m = m0 + row8 + i;
        int b_ = m >> 11, t = m & 2047;
        float* p = dst + ((size_t)((b_ * HH + h) * TT + t)) * DD + dd;
        *(float4*)p = make_float4(acc[0] + bvv[0], acc[1] + bvv[1],
                                  acc[2] + bvv[2], acc[3] + bvv[3]);
        *(float4*)(p + 4) = make_float4(acc[4] + bvv[4], acc[5] + bvv[5],
                                        acc[6] + bvv[6], acc[7] + bvv[7]);
    }
}

__global__ __launch_bounds__(256, 2)
void proj_p2_kernel(const float* __restrict__ Wg, const float* __restrict__ bias,
                    float* __restrict__ out)
{
    __shared__ float As[2][8][132];
    __shared__ float Bs[2][8][132];

    const int tid  = threadIdx.x;
    const int ty   = tid >> 4, tx = tid & 15;
    const int row8 = ty * 8,  col8 = tx * 8;
    const int m0   = blockIdx.y * 128;
    const int n0   = blockIdx.x * 128;

    const int ar = tid >> 1;
    const int aq = (tid & 1) * 4;
    const int bk = tid >> 5;
    const int bc = tid & 31;
    const int bj = (((bc & 15) << 1) | (bc >> 4)) * 4;

    const size_t bstride = (size_t)8 * CC;
    const float* aptr = g_y + (size_t)(m0 + ar) * 1024 + aq;   // symbol access
    const float* bptr = Wg + (size_t)bk * CC + n0 + bj;

    u64 acc2[8][4];
#pragma unroll
    for (int i = 0; i < 8; i++)
#pragma unroll
        for (int j = 0; j < 4; j++) acc2[i][j] = 0ull;

    {
        float4 av = *(const float4*)aptr;
        float4 bv = *(const float4*)bptr;
        As[0][aq + 0][ar] = av.x; As[0][aq + 1][ar] = av.y;
        As[0][aq + 2][ar] = av.z; As[0][aq + 3][ar] = av.w;
        *(float4*)&Bs[0][bk][4 * bc] = bv;
        aptr += 8;
        bptr += bstride;
    }
    __syncthreads();

    for (int s = 0; s < 63; s++) {
        GEMM_PHASE(0, 1, false);
        GEMM_PHASE(1, 0, false);
    }
    GEMM_PHASE(0, 1, false);
    GEMM_PHASE(1, 0, true);

    float bvv[8];
#pragma unroll
    for (int j = 0; j < 8; j++) bvv[j] = bias[n0 + col8 + j];
#pragma unroll
    for (int i = 0; i < 8; i++) {
        float acc[8];
#pragma unroll
        for (int jp = 0; jp < 4; jp++)
            unpack2(acc2[i][jp], acc[2 * jp], acc[2 * jp + 1]);
        int m = m0 + row8 + i;
        float* p = out + (size_t)m * CC + n0 + col8;
        *(float4*)p = make_float4(acc[0] + bvv[0], acc[1] + bvv[1],
                                  acc[2] + bvv[2], acc[3] + bvv[3]);
        *(float4*)(p + 4) = make_float4(acc[4] + bvv[4], acc[5] + bvv[5],
                                        acc[6] + bvv[6], acc[7] + bvv[7]);
    }
}

// ---------------------------------------------------------------------------
// Kernel 2: Flash attention — BYTE-IDENTICAL to the Round-15/16 winner
// (packed f32x2, cp.async V, own Ps buffer, heavy-first grid).
// ---------------------------------------------------------------------------
#define ATTN_SMEM_FLOATS (64*132 + 64*68 + 64*68 + 128*68)
#define ATTN_SMEM_BYTES  (ATTN_SMEM_FLOATS * 4)

__global__ __launch_bounds__(256, 2)
void attn_kernel()
{
    extern __shared__ float smem[];
    float (*Qt)[132] = (float(*)[132])smem;                        // [d][query]
    float (*Kt)[68]  = (float(*)[68])(smem + 64 * 132);            // [d][key]
    float (*Vs)[68]  = (float(*)[68])(smem + 64 * 132 + 64 * 68);  // [key][d]
    float (*Ps)[68]  = (float(*)[68])(smem + 64 * 132 + 2 * 64 * 68); // [q][key]

    const int tid  = threadIdx.x;
    const int ty   = tid >> 4, tx = tid & 15;
    const int row8 = ty * 8;
    const int col4 = tx * 4;

    const int q0 = (gridDim.y - 1 - blockIdx.y) * 128;   // heavy-first
    const int bh = blockIdx.x;        // b*16 + h
    const float* qbase = g_q + ((size_t)bh * TT + q0) * DD;
    const uint32_t vs_base = smem_u32_of(&Vs[0][0]);

    const float scale = 0.125f;
#pragma unroll
    for (int it = 0; it < 8; it++) {
        int idx = tid + 256 * it;
        int r   = idx >> 4;
        int dq  = (idx & 15) * 4;
        float4 v = *(const float4*)(qbase + (size_t)r * DD + dq);
        Qt[dq + 0][r] = v.x * scale; Qt[dq + 1][r] = v.y * scale;
        Qt[dq + 2][r] = v.z * scale; Qt[dq + 3][r] = v.w * scale;
    }

    float m_i[8], l_i[8];
    u64 O2[8][2];
#pragma unroll
    for (int i = 0; i < 8; i++) {
        m_i[i] = -1e30f; l_i[i] = 0.f;
        O2[i][0] = 0ull; O2[i][1] = 0ull;
    }

    const int maskStart = q0 >> 6;
    const int nblk      = maskStart + 2;

    for (int kb = 0; kb < nblk; kb++) {
        __syncthreads();

        {
            const float* vb = g_v + ((size_t)bh * TT + kb * 64) * DD;
#pragma unroll
            for (int it = 0; it < 4; it++) {
                int idx = tid + 256 * it;
                int r   = idx >> 4;
                int dq  = (idx & 15) * 4;
                CPG16(vs_base + (r * 68 + dq) * 4, vb + (size_t)r * DD + dq);
            }
            CP_COMMIT();
        }

        {
            const float* kbase = g_k + ((size_t)bh * TT + kb * 64) * DD;
#pragma unroll
            for (int it = 0; it < 4; it++) {
                int idx = tid + 256 * it;
                int r   = idx >> 4;
                int dq  = (idx & 15) * 4;
                float4 kv = *(const float4*)(kbase + (size_t)r * DD + dq);
                Kt[dq + 0][r] = kv.x; Kt[dq + 1][r] = kv.y;
                Kt[dq + 2][r] = kv.z; Kt[dq + 3][r] = kv.w;
            }
        }
        __syncthreads();

        u64 s2[4][4];
#pragma unroll
        for (int p = 0; p < 4; p++)
#pragma unroll
            for (int j = 0; j < 4; j++) s2[p][j] = 0ull;

#pragma unroll 4
        for (int dd = 0; dd < 64; dd++) {
            float4 a0 = *(float4*)&Qt[dd][row8];
            float4 a1 = *(float4*)&Qt[dd][row8 + 4];
            u64 qp[4];
            qp[0] = ((const u64*)&a0)[0];
            qp[1] = ((const u64*)&a0)[1];
            qp[2] = ((const u64*)&a1)[0];
            qp[3] = ((const u64*)&a1)[1];
            float4 bq = *(float4*)&Kt[dd][col4];
            u64 k0 = pack2(bq.x), k1 = pack2(bq.y),
                k2 = pack2(bq.z), k3 = pack2(bq.w);
#pragma unroll
            for (int p = 0; p < 4; p++) {
                ffma2(s2[p][0], qp[p], k0);
                ffma2(s2[p][1], qp[p], k1);
                ffma2(s2[p][2], qp[p], k2);
                ffma2(s2[p][3], qp[p], k3);
            }
        }

        float s[8][4];
#pragma unroll
        for (int p = 0; p < 4; p++)
#pragma unroll
            for (int j = 0; j < 4; j++)
                unpack2(s2[p][j], s[2 * p][j], s[2 * p + 1][j]);

        if (kb >= maskStart) {
#pragma unroll
            for (int i = 0; i < 8; i++) {
                int gq = q0 + row8 + i;
#pragma unroll
                for (int j = 0; j < 4; j++) {
                    int gk = kb * 64 + col4 + j;
                    if (gk > gq) s[i][j] = -1e30f;
                }
            }
        }

#pragma unroll
        for (int i = 0; i < 8; i++) {
            float v = fmaxf(fmaxf(s[i][0], s[i][1]), fmaxf(s[i][2], s[i][3]));
#pragma unroll
            for (int o = 1; o < 16; o <<= 1)
                v = fmaxf(v, __shfl_xor_sync(0xffffffffu, v, o));
            float mnew  = fmaxf(m_i[i], v);
            float alpha = __expf(m_i[i] - mnew);
            m_i[i] = mnew;
            float ps = 0.f;
#pragma unroll
            for (int j = 0; j < 4; j++) {
                s[i][j] = __expf(s[i][j] - mnew);
                ps += s[i][j];
            }
#pragma unroll
            for (int o = 1; o < 16; o <<= 1)
                ps += __shfl_xor_sync(0xffffffffu, ps, o);
            l_i[i] = l_i[i] * alpha + ps;
            u64 ap = pack2(alpha);
            fmul2(O2[i][0], ap);
            fmul2(O2[i][1], ap);
        }

#pragma unroll
        for (int i = 0; i < 8; i++)
            *(float4*)&Ps[row8 + i][col4] =
                make_float4(s[i][0], s[i][1], s[i][2], s[i][3]);

        CP_WAIT0();
        __syncthreads();

#pragma unroll 2
        for (int j = 0; j < 64; j += 4) {
            float4 pa[8];
#pragma unroll
            for (int i = 0; i < 8; i++) pa[i] = *(float4*)&Ps[row8 + i][j];
            float4 b0 = *(float4*)&Vs[j + 0][col4];
            float4 b1 = *(float4*)&Vs[j + 1][col4];
            float4 b2 = *(float4*)&Vs[j + 2][col4];
            float4 b3 = *(float4*)&Vs[j + 3][col4];
            u64 bp[4][2];
            bp[0][0] = ((const u64*)&b0)[0]; bp[0][1] = ((const u64*)&b0)[1];
            bp[1][0] = ((const u64*)&b1)[0]; bp[1][1] = ((const u64*)&b1)[1];
            bp[2][0] = ((const u64*)&b2)[0]; bp[2][1] = ((const u64*)&b2)[1];
            bp[3][0] = ((const u64*)&b3)[0]; bp[3][1] = ((const u64*)&b3)[1];
#pragma unroll
            for (int i = 0; i < 8; i++) {
                u64 ap;
                ap = pack2(pa[i].x);
                ffma2(O2[i][0], ap, bp[0][0]); ffma2(O2[i][1], ap, bp[0][1]);
                ap = pack2(pa[i].y);
                ffma2(O2[i][0], ap, bp[1][0]); ffma2(O2[i][1], ap, bp[1][1]);
                ap = pack2(pa[i].z);
                ffma2(O2[i][0], ap, bp[2][0]); ffma2(O2[i][1], ap, bp[2][1]);
                ap = pack2(pa[i].w);
                ffma2(O2[i][0], ap, bp[3][0]); ffma2(O2[i][1], ap, bp[3][1]);
            }
        }
    }

    const int b = bh >> 4, h = bh & 15;
#pragma unroll
    for (int i = 0; i < 8; i++) {
        float inv = 1.f / l_i[i];
        float o0, o1, o2, o3;
        unpack2(O2[i][0], o0, o1);
        unpack2(O2[i][1], o2, o3);
        int t = q0 + row8 + i;
        float* p = g_y + ((size_t)b * TT + t) * CC + h * DD + col4;
        *(float4*)p = make_float4(o0 * inv, o1 * inv, o2 * inv, o3 * inv);
    }
}

// ---------------------------------------------------------------------------
extern "C" void kernel_launch(void* const* d_in, const int* in_sizes, int n_in,
                              void* d_out, int out_size)
{
    (void)in_sizes; (void)n_in; (void)out_size;
    const float* x      = (const float*)d_in[0];
    const float* W_attn = (const float*)d_in[1];
    const float* b_attn = (const float*)d_in[2];
    const float* W_proj = (const float*)d_in[3];
    const float* b_proj = (const float*)d_in[4];
    float* out = (float*)d_out;

    cudaFuncSetAttribute(attn_kernel,
                         cudaFuncAttributeMaxDynamicSharedMemorySize,
                         ATTN_SMEM_BYTES);

    qkv_p2_kernel <<<dim3(3072 / 128, MROWS / 128), 256>>>(x, W_attn, b_attn);
    attn_kernel   <<<dim3(BB * HH, TT / 128), 256, ATTN_SMEM_BYTES>>>();
    proj_p2_kernel<<<dim3(CC / 128, MROWS / 128), 256>>>(W_proj, b_proj, out);
}